// round 1
// baseline (speedup 1.0000x reference)
#include <cuda_runtime.h>
#include <cstdint>

#define T_TOK 4096
#define H_DIM 2048
#define I_DIM 4096
#define N_EXP 8
#define TOPK 2
#define N_SLOTS (T_TOK * TOPK)

#define BM 128
#define BN 64
#define BK 32
#define AS_STRIDE (BK + 4)          // 36 floats -> conflict-free fragment LDS
#define MAX_MT (N_SLOTS / BM)        // 64 tiles worst case per expert

// ---------------- scratch (static device globals; no allocation) ------------
__device__ int   g_cnt[N_EXP];
__device__ int   g_cur[N_EXP];
__device__ int   g_off[N_EXP + 1];
__device__ int   g_tok_e[N_SLOTS];
__device__ float g_tok_w[N_SLOTS];
__device__ int   g_slot_tok[N_SLOTS];
__device__ float g_slot_w[N_SLOTS];
__device__ float g_act[(size_t)N_SLOTS * I_DIM];   // silu(gate)*up, fp32

// ---------------- helpers ----------------------------------------------------
__device__ __forceinline__ float to_tf32(float x) {
    uint32_t u;
    asm("cvt.rna.tf32.f32 %0, %1;" : "=r"(u) : "f"(x));
    return __uint_as_float(u);
}

__device__ __forceinline__ void mma_tf32(float c[4], const uint32_t a[4],
                                         const uint32_t b[2]) {
    asm("mma.sync.aligned.m16n8k8.row.col.f32.tf32.tf32.f32 "
        "{%0,%1,%2,%3}, {%4,%5,%6,%7}, {%8,%9}, {%0,%1,%2,%3};"
        : "+f"(c[0]), "+f"(c[1]), "+f"(c[2]), "+f"(c[3])
        : "r"(a[0]), "r"(a[1]), "r"(a[2]), "r"(a[3]),
          "r"(b[0]), "r"(b[1]));
}

// ---------------- routing ----------------------------------------------------
__global__ void reset_kernel() {
    int i = threadIdx.x;
    if (i < N_EXP) { g_cnt[i] = 0; g_cur[i] = 0; }
}

__global__ void route_kernel(const float* __restrict__ logits) {
    int t = blockIdx.x * blockDim.x + threadIdx.x;
    if (t >= T_TOK) return;
    float v[N_EXP];
#pragma unroll
    for (int e = 0; e < N_EXP; e++) v[e] = logits[t * N_EXP + e];

    int e0 = 0; float b0 = v[0];
#pragma unroll
    for (int e = 1; e < N_EXP; e++) if (v[e] > b0) { b0 = v[e]; e0 = e; }
    int e1 = -1; float b1 = -3.0e38f;
#pragma unroll
    for (int e = 0; e < N_EXP; e++)
        if (e != e0 && v[e] > b1) { b1 = v[e]; e1 = e; }

    // softmax over the two selected logits
    float w1v = __expf(b1 - b0);
    float inv = 1.0f / (1.0f + w1v);
    g_tok_e[2 * t]     = e0;
    g_tok_e[2 * t + 1] = e1;
    g_tok_w[2 * t]     = inv;
    g_tok_w[2 * t + 1] = w1v * inv;
    atomicAdd(&g_cnt[e0], 1);
    atomicAdd(&g_cnt[e1], 1);
}

__global__ void scan_kernel() {
    int acc = 0;
    g_off[0] = 0;
#pragma unroll
    for (int e = 0; e < N_EXP; e++) { acc += g_cnt[e]; g_off[e + 1] = acc; }
}

__global__ void scatter_kernel() {
    int t = blockIdx.x * blockDim.x + threadIdx.x;
    if (t >= T_TOK) return;
#pragma unroll
    for (int k = 0; k < TOPK; k++) {
        int e = g_tok_e[2 * t + k];
        int p = atomicAdd(&g_cur[e], 1);
        int s = g_off[e] + p;
        g_slot_tok[s] = t;
        g_slot_w[s]   = g_tok_w[2 * t + k];
    }
}

// ---------------- phase B: act = silu(x @ w1^T) * (x @ w3^T) -----------------
__global__ __launch_bounds__(256, 2)
void gateup_kernel(const float* __restrict__ hidden,
                   const float* __restrict__ w1,
                   const float* __restrict__ w3) {
    __shared__ float As[BM][AS_STRIDE];
    __shared__ float B1s[BN][AS_STRIDE];
    __shared__ float B3s[BN][AS_STRIDE];
    __shared__ int   s_tok[BM];

    int e  = blockIdx.y / MAX_MT;
    int mt = blockIdx.y % MAX_MT;
    int slot0    = g_off[e] + mt * BM;
    int slot_end = g_off[e + 1];
    if (slot0 >= slot_end) return;
    int n_valid = slot_end - slot0;
    if (n_valid > BM) n_valid = BM;
    int i0 = blockIdx.x * BN;

    int tid   = threadIdx.x;
    int lane  = tid & 31;
    int warp  = tid >> 5;
    int warpM = warp & 3;   // 4 warps x 32 rows = 128
    int warpN = warp >> 2;  // 2 warps x 32 cols = 64

    for (int r = tid; r < BM; r += 256)
        s_tok[r] = (r < n_valid) ? g_slot_tok[slot0 + r] : 0;
    __syncthreads();

    float accg[2][4][4] = {};
    float accu[2][4][4] = {};

    int c4 = tid & 7;   // which float4 in the 32-wide K slab
    int rr = tid >> 3;  // 0..31

    const float* w1b = w1 + ((size_t)e * I_DIM + i0) * H_DIM;
    const float* w3b = w3 + ((size_t)e * I_DIM + i0) * H_DIM;

    for (int k0 = 0; k0 < H_DIM; k0 += BK) {
        // A tile: 128 gathered rows x 32 cols
#pragma unroll
        for (int j = 0; j < 4; j++) {
            int r = rr + j * 32;
            const float4 v = *reinterpret_cast<const float4*>(
                hidden + (size_t)s_tok[r] * H_DIM + k0 + c4 * 4);
            float4 tv = make_float4(to_tf32(v.x), to_tf32(v.y),
                                    to_tf32(v.z), to_tf32(v.w));
            *reinterpret_cast<float4*>(&As[r][c4 * 4]) = tv;
        }
        // B tiles: 64 rows x 32 cols each for w1 and w3
#pragma unroll
        for (int j = 0; j < 2; j++) {
            int n = rr + j * 32;
            const float4 v1 = *reinterpret_cast<const float4*>(
                w1b + (size_t)n * H_DIM + k0 + c4 * 4);
            const float4 v3 = *reinterpret_cast<const float4*>(
                w3b + (size_t)n * H_DIM + k0 + c4 * 4);
            *reinterpret_cast<float4*>(&B1s[n][c4 * 4]) =
                make_float4(to_tf32(v1.x), to_tf32(v1.y), to_tf32(v1.z), to_tf32(v1.w));
            *reinterpret_cast<float4*>(&B3s[n][c4 * 4]) =
                make_float4(to_tf32(v3.x), to_tf32(v3.y), to_tf32(v3.z), to_tf32(v3.w));
        }
        __syncthreads();

#pragma unroll
        for (int kk = 0; kk < BK; kk += 8) {
            uint32_t a[2][4];
#pragma unroll
            for (int m = 0; m < 2; m++) {
                int rbase = warpM * 32 + m * 16 + (lane >> 2);
                int kbase = kk + (lane & 3);
                a[m][0] = __float_as_uint(As[rbase][kbase]);
                a[m][1] = __float_as_uint(As[rbase + 8][kbase]);
                a[m][2] = __float_as_uint(As[rbase][kbase + 4]);
                a[m][3] = __float_as_uint(As[rbase + 8][kbase + 4]);
            }
#pragma unroll
            for (int nt = 0; nt < 4; nt++) {
                int nb = warpN * 32 + nt * 8 + (lane >> 2);
                int kb = kk + (lane & 3);
                uint32_t b1[2] = {__float_as_uint(B1s[nb][kb]),
                                  __float_as_uint(B1s[nb][kb + 4])};
                uint32_t b3[2] = {__float_as_uint(B3s[nb][kb]),
                                  __float_as_uint(B3s[nb][kb + 4])};
#pragma unroll
                for (int m = 0; m < 2; m++) {
                    mma_tf32(accg[m][nt], a[m], b1);
                    mma_tf32(accu[m][nt], a[m], b3);
                }
            }
        }
        __syncthreads();
    }

    // epilogue: silu(gate) * up -> g_act
#pragma unroll
    for (int m = 0; m < 2; m++) {
        int row0 = warpM * 32 + m * 16 + (lane >> 2);
#pragma unroll
        for (int nt = 0; nt < 4; nt++) {
            int col = i0 + warpN * 32 + nt * 8 + (lane & 3) * 2;
            if (row0 < n_valid) {
                size_t base = (size_t)(slot0 + row0) * I_DIM + col;
                float g0 = accg[m][nt][0], u0 = accu[m][nt][0];
                g_act[base]     = (g0 / (1.0f + __expf(-g0))) * u0;
                float g1 = accg[m][nt][1], u1 = accu[m][nt][1];
                g_act[base + 1] = (g1 / (1.0f + __expf(-g1))) * u1;
            }
            if (row0 + 8 < n_valid) {
                size_t base = (size_t)(slot0 + row0 + 8) * I_DIM + col;
                float g2 = accg[m][nt][2], u2 = accu[m][nt][2];
                g_act[base]     = (g2 / (1.0f + __expf(-g2))) * u2;
                float g3 = accg[m][nt][3], u3 = accu[m][nt][3];
                g_act[base + 1] = (g3 / (1.0f + __expf(-g3))) * u3;
            }
        }
    }
}

// ---------------- phase C: out[t] += w_slot * (act @ w2^T) -------------------
__global__ __launch_bounds__(256, 2)
void down_kernel(const float* __restrict__ w2, float* __restrict__ out) {
    __shared__ float As[BM][AS_STRIDE];
    __shared__ float Bs[BN][AS_STRIDE];
    __shared__ int   s_tok[BM];
    __shared__ float s_w[BM];

    int e  = blockIdx.y / MAX_MT;
    int mt = blockIdx.y % MAX_MT;
    int slot0    = g_off[e] + mt * BM;
    int slot_end = g_off[e + 1];
    if (slot0 >= slot_end) return;
    int n_valid = slot_end - slot0;
    if (n_valid > BM) n_valid = BM;
    int h0 = blockIdx.x * BN;

    int tid   = threadIdx.x;
    int lane  = tid & 31;
    int warp  = tid >> 5;
    int warpM = warp & 3;
    int warpN = warp >> 2;

    for (int r = tid; r < BM; r += 256) {
        bool ok = (r < n_valid);
        s_tok[r] = ok ? g_slot_tok[slot0 + r] : 0;
        s_w[r]   = ok ? g_slot_w[slot0 + r] : 0.0f;
    }
    __syncthreads();

    float acc[2][4][4] = {};

    int c4 = tid & 7;
    int rr = tid >> 3;

    const float* w2b = w2 + ((size_t)e * H_DIM + h0) * I_DIM;

    for (int k0 = 0; k0 < I_DIM; k0 += BK) {
#pragma unroll
        for (int j = 0; j < 4; j++) {
            int r  = rr + j * 32;
            int sr = slot0 + r;
            if (sr >= N_SLOTS) sr = N_SLOTS - 1;   // clamp OOB reads
            const float4 v = *reinterpret_cast<const float4*>(
                g_act + (size_t)sr * I_DIM + k0 + c4 * 4);
            *reinterpret_cast<float4*>(&As[r][c4 * 4]) =
                make_float4(to_tf32(v.x), to_tf32(v.y), to_tf32(v.z), to_tf32(v.w));
        }
#pragma unroll
        for (int j = 0; j < 2; j++) {
            int n = rr + j * 32;
            const float4 v = *reinterpret_cast<const float4*>(
                w2b + (size_t)n * I_DIM + k0 + c4 * 4);
            *reinterpret_cast<float4*>(&Bs[n][c4 * 4]) =
                make_float4(to_tf32(v.x), to_tf32(v.y), to_tf32(v.z), to_tf32(v.w));
        }
        __syncthreads();

#pragma unroll
        for (int kk = 0; kk < BK; kk += 8) {
            uint32_t a[2][4];
#pragma unroll
            for (int m = 0; m < 2; m++) {
                int rbase = warpM * 32 + m * 16 + (lane >> 2);
                int kbase = kk + (lane & 3);
                a[m][0] = __float_as_uint(As[rbase][kbase]);
                a[m][1] = __float_as_uint(As[rbase + 8][kbase]);
                a[m][2] = __float_as_uint(As[rbase][kbase + 4]);
                a[m][3] = __float_as_uint(As[rbase + 8][kbase + 4]);
            }
#pragma unroll
            for (int nt = 0; nt < 4; nt++) {
                int nb = warpN * 32 + nt * 8 + (lane >> 2);
                int kb = kk + (lane & 3);
                uint32_t b[2] = {__float_as_uint(Bs[nb][kb]),
                                 __float_as_uint(Bs[nb][kb + 4])};
#pragma unroll
                for (int m = 0; m < 2; m++) mma_tf32(acc[m][nt], a[m], b);
            }
        }
        __syncthreads();
    }

    // epilogue: scaled atomic scatter-add into out[token, h]
#pragma unroll
    for (int m = 0; m < 2; m++) {
        int row0 = warpM * 32 + m * 16 + (lane >> 2);
#pragma unroll
        for (int nt = 0; nt < 4; nt++) {
            int col = h0 + warpN * 32 + nt * 8 + (lane & 3) * 2;
            if (row0 < n_valid) {
                int t  = s_tok[row0];
                float w = s_w[row0];
                atomicAdd(&out[(size_t)t * H_DIM + col],     w * acc[m][nt][0]);
                atomicAdd(&out[(size_t)t * H_DIM + col + 1], w * acc[m][nt][1]);
            }
            if (row0 + 8 < n_valid) {
                int t  = s_tok[row0 + 8];
                float w = s_w[row0 + 8];
                atomicAdd(&out[(size_t)t * H_DIM + col],     w * acc[m][nt][2]);
                atomicAdd(&out[(size_t)t * H_DIM + col + 1], w * acc[m][nt][3]);
            }
        }
    }
}

// ---------------- launch ------------------------------------------------------
extern "C" void kernel_launch(void* const* d_in, const int* in_sizes, int n_in,
                              void* d_out, int out_size) {
    const float* hidden = (const float*)d_in[0];
    const float* logits = (const float*)d_in[1];
    const float* w1     = (const float*)d_in[2];
    const float* w3     = (const float*)d_in[3];
    const float* w2     = (const float*)d_in[4];
    float* out = (float*)d_out;

    cudaMemsetAsync(out, 0, (size_t)T_TOK * H_DIM * sizeof(float), 0);

    reset_kernel<<<1, 32>>>();
    route_kernel<<<T_TOK / 256, 256>>>(logits);
    scan_kernel<<<1, 1>>>();
    scatter_kernel<<<T_TOK / 256, 256>>>();

    dim3 gB(I_DIM / BN, N_EXP * MAX_MT);
    gateup_kernel<<<gB, 256>>>(hidden, w1, w3);

    dim3 gC(H_DIM / BN, N_EXP * MAX_MT);
    down_kernel<<<gC, 256>>>(w2, out);
}

// round 3
// speedup vs baseline: 1.3194x; 1.3194x over previous
#include <cuda_runtime.h>
#include <cstdint>

#define T_TOK 4096
#define H_DIM 2048
#define I_DIM 4096
#define N_EXP 8
#define TOPK 2
#define N_SLOTS (T_TOK * TOPK)

#define BK 32
#define RS 36                    // SMEM row stride in floats (144B, 16B-aligned, conflict-free)
#define TILE_F (128 * RS)        // 4608 floats per 128x32 tile
#define TILE_B (TILE_F * 4)      // 18432 bytes
#define MT 32                    // max m-tiles per expert (worst case 4096 tokens)

#define GU_STAGES 4
#define GU_STAGE_F (3 * TILE_F)  // A + Bgate + Bup
#define GU_STAGE_B (GU_STAGE_F * 4)
#define GU_SMEM (GU_STAGES * GU_STAGE_B)   // 221184
#define ITILES (I_DIM / 128)     // 32
#define KT_GU (H_DIM / BK)       // 64

#define DN_STAGES 4
#define DN_STAGE_F (2 * TILE_F)  // A + B
#define DN_STAGE_B (DN_STAGE_F * 4)
#define DN_SMEM (DN_STAGES * DN_STAGE_B)   // 147456
#define HTILES (H_DIM / 128)     // 16
#define KT_DN (I_DIM / BK)       // 128

// ---------------- scratch (static device globals; no allocation) ------------
__device__ int   g_cnt[N_EXP];
__device__ int   g_cur[N_EXP];
__device__ int   g_off[N_EXP + 1];
__device__ int   g_tok_e[N_SLOTS];
__device__ float g_tok_w[N_SLOTS];
__device__ int   g_slot_tok[N_SLOTS];
__device__ float g_slot_w[N_SLOTS];
__device__ float g_act[(size_t)N_SLOTS * I_DIM];                 // 128MB
__device__ float g_w1r[(size_t)N_EXP * I_DIM * H_DIM];           // 256MB tf32-rounded
__device__ float g_w3r[(size_t)N_EXP * I_DIM * H_DIM];           // 256MB
__device__ float g_w2r[(size_t)N_EXP * H_DIM * I_DIM];           // 256MB
__device__ float g_hidr[(size_t)T_TOK * H_DIM];                  // 32MB

// ---------------- helpers ----------------------------------------------------
__device__ __forceinline__ float tf32r(float x) {
    uint32_t u; asm("cvt.rna.tf32.f32 %0, %1;" : "=r"(u) : "f"(x));
    return __uint_as_float(u);
}
__device__ __forceinline__ uint32_t smem_u32(const void* p) {
    uint32_t a;
    asm("{ .reg .u64 t; cvta.to.shared.u64 t, %1; cvt.u32.u64 %0, t; }"
        : "=r"(a) : "l"(p));
    return a;
}
__device__ __forceinline__ void cpa16(uint32_t dst, const void* src) {
    asm volatile("cp.async.cg.shared.global [%0], [%1], 16;"
                 :: "r"(dst), "l"(src));
}
#define CP_COMMIT() asm volatile("cp.async.commit_group;" ::: "memory")
#define CP_WAIT3()  asm volatile("cp.async.wait_group 3;" ::: "memory")

__device__ __forceinline__ void mma_tf32(float c[4], const uint32_t a[4],
                                         const uint32_t b[2]) {
    asm("mma.sync.aligned.m16n8k8.row.col.f32.tf32.tf32.f32 "
        "{%0,%1,%2,%3}, {%4,%5,%6,%7}, {%8,%9}, {%0,%1,%2,%3};"
        : "+f"(c[0]), "+f"(c[1]), "+f"(c[2]), "+f"(c[3])
        : "r"(a[0]), "r"(a[1]), "r"(a[2]), "r"(a[3]),
          "r"(b[0]), "r"(b[1]));
}

// ---------------- routing ----------------------------------------------------
__global__ void reset_kernel() {
    int i = threadIdx.x;
    if (i < N_EXP) { g_cnt[i] = 0; g_cur[i] = 0; }
}

__global__ void route_kernel(const float* __restrict__ logits) {
    int t = blockIdx.x * blockDim.x + threadIdx.x;
    if (t >= T_TOK) return;
    float v[N_EXP];
#pragma unroll
    for (int e = 0; e < N_EXP; e++) v[e] = logits[t * N_EXP + e];
    int e0 = 0; float b0 = v[0];
#pragma unroll
    for (int e = 1; e < N_EXP; e++) if (v[e] > b0) { b0 = v[e]; e0 = e; }
    int e1 = -1; float b1 = -3.0e38f;
#pragma unroll
    for (int e = 0; e < N_EXP; e++)
        if (e != e0 && v[e] > b1) { b1 = v[e]; e1 = e; }
    float w1v = __expf(b1 - b0);
    float inv = 1.0f / (1.0f + w1v);
    g_tok_e[2 * t]     = e0;
    g_tok_e[2 * t + 1] = e1;
    g_tok_w[2 * t]     = inv;
    g_tok_w[2 * t + 1] = w1v * inv;
    atomicAdd(&g_cnt[e0], 1);
    atomicAdd(&g_cnt[e1], 1);
}

__global__ void scan_kernel() {
    int acc = 0;
    g_off[0] = 0;
#pragma unroll
    for (int e = 0; e < N_EXP; e++) { acc += g_cnt[e]; g_off[e + 1] = acc; }
}

__global__ void scatter_kernel() {
    int t = blockIdx.x * blockDim.x + threadIdx.x;
    if (t >= T_TOK) return;
#pragma unroll
    for (int k = 0; k < TOPK; k++) {
        int e = g_tok_e[2 * t + k];
        int p = atomicAdd(&g_cur[e], 1);
        int s = g_off[e] + p;
        g_slot_tok[s] = t;
        g_slot_w[s]   = g_tok_w[2 * t + k];
    }
}

// ---------------- pre-round: RNA tf32 copies of weights + hidden -------------
#define W_F4 (16777216)          // 64M floats / 4
#define H_F4 (2097152)           // 8M floats / 4
#define RND_BLOCKS ((3 * W_F4 + H_F4) / 256)

__global__ void round_all(const float4* __restrict__ w1,
                          const float4* __restrict__ w3,
                          const float4* __restrict__ w2,
                          const float4* __restrict__ hid) {
    long long i = (long long)blockIdx.x * 256 + threadIdx.x;
    const float4* s;
    float4* d;
    if (i < W_F4)            { s = w1 + i;              d = (float4*)g_w1r + i; }
    else if (i < 2 * W_F4)   { s = w3 + (i - W_F4);     d = (float4*)g_w3r + (i - W_F4); }
    else if (i < 3 * W_F4)   { s = w2 + (i - 2 * W_F4); d = (float4*)g_w2r + (i - 2 * W_F4); }
    else                     { s = hid + (i - 3 * W_F4); d = (float4*)g_hidr + (i - 3 * W_F4); }
    float4 v = *s;
    *d = make_float4(tf32r(v.x), tf32r(v.y), tf32r(v.z), tf32r(v.w));
}

// ---------------- phase B: act = silu(x @ w1^T) * (x @ w3^T) -----------------
// BM=128 slots, BN=128 intermediate cols (gate+up), BK=32, 256 thr.
// warp tile 64x32 (x2 for gate/up). warpM = warp&1, warpN = warp>>1.
__device__ __forceinline__ void gu_load(uint32_t sb, int e, int i0,
                                        const int* stok, int k0) {
    int tid = threadIdx.x;
    const float* w1p = g_w1r + ((size_t)e * I_DIM + i0) * H_DIM + k0;
    const float* w3p = g_w3r + ((size_t)e * I_DIM + i0) * H_DIM + k0;
#pragma unroll
    for (int j = 0; j < 4; j++) {
        int idx = tid + j * 256;
        int row = idx >> 3, sl = idx & 7;
        cpa16(sb + (uint32_t)(row * 144 + sl * 16),
              g_hidr + (size_t)stok[row] * H_DIM + k0 + sl * 4);
    }
#pragma unroll
    for (int j = 0; j < 4; j++) {
        int idx = tid + j * 256;
        int row = idx >> 3, sl = idx & 7;
        cpa16(sb + TILE_B + (uint32_t)(row * 144 + sl * 16),
              w1p + (size_t)row * H_DIM + sl * 4);
    }
#pragma unroll
    for (int j = 0; j < 4; j++) {
        int idx = tid + j * 256;
        int row = idx >> 3, sl = idx & 7;
        cpa16(sb + 2 * TILE_B + (uint32_t)(row * 144 + sl * 16),
              w3p + (size_t)row * H_DIM + sl * 4);
    }
}

__global__ __launch_bounds__(256, 1)
void gateup_lg() {
    extern __shared__ float sm[];
    __shared__ int s_tok[128];

    int e  = blockIdx.y >> 5;
    int it = blockIdx.y & 31;
    int mt = blockIdx.x;
    int slot0 = g_off[e] + mt * 128;
    int send  = g_off[e + 1];
    if (slot0 >= send) return;
    int n_valid = min(128, send - slot0);
    int i0 = it * 128;

    int tid = threadIdx.x, lane = tid & 31, warp = tid >> 5;
    int warpM = warp & 1, warpN = warp >> 1;

    for (int r = tid; r < 128; r += 256)
        s_tok[r] = (r < n_valid) ? g_slot_tok[slot0 + r] : g_slot_tok[slot0];
    __syncthreads();

    uint32_t sb0 = smem_u32(sm);
#pragma unroll
    for (int s = 0; s < GU_STAGES - 1; s++) {
        if (s < KT_GU) gu_load(sb0 + s * GU_STAGE_B, e, i0, s_tok, s * BK);
        CP_COMMIT();
    }

    float accg[4][4][4] = {};
    float accu[4][4][4] = {};
    int r4 = lane >> 2;

    for (int kt = 0; kt < KT_GU; kt++) {
        int ldk = kt + GU_STAGES - 1;
        if (ldk < KT_GU)
            gu_load(sb0 + (ldk % GU_STAGES) * GU_STAGE_B, e, i0, s_tok, ldk * BK);
        CP_COMMIT();
        CP_WAIT3();
        __syncthreads();

        const float* As = sm + (kt % GU_STAGES) * GU_STAGE_F;
        const float* Bg = As + TILE_F;
        const float* Bu = As + 2 * TILE_F;

#pragma unroll
        for (int kk = 0; kk < 32; kk += 8) {
            int kb = kk + (lane & 3);
            uint32_t a[4][4];
#pragma unroll
            for (int m = 0; m < 4; m++) {
                int rb = warpM * 64 + m * 16 + r4;
                a[m][0] = __float_as_uint(As[rb * RS + kb]);
                a[m][1] = __float_as_uint(As[(rb + 8) * RS + kb]);
                a[m][2] = __float_as_uint(As[rb * RS + kb + 4]);
                a[m][3] = __float_as_uint(As[(rb + 8) * RS + kb + 4]);
            }
#pragma unroll
            for (int nt = 0; nt < 4; nt++) {
                int nb = warpN * 32 + nt * 8 + r4;
                uint32_t bg[2] = {__float_as_uint(Bg[nb * RS + kb]),
                                  __float_as_uint(Bg[nb * RS + kb + 4])};
                uint32_t bu[2] = {__float_as_uint(Bu[nb * RS + kb]),
                                  __float_as_uint(Bu[nb * RS + kb + 4])};
#pragma unroll
                for (int m = 0; m < 4; m++) {
                    mma_tf32(accg[m][nt], a[m], bg);
                    mma_tf32(accu[m][nt], a[m], bu);
                }
            }
        }
        __syncthreads();
    }

    // epilogue: silu(gate)*up -> g_act (tf32-rounded)
#pragma unroll
    for (int m = 0; m < 4; m++) {
#pragma unroll
        for (int nt = 0; nt < 4; nt++) {
            int r0 = warpM * 64 + m * 16 + r4;
            int c  = i0 + warpN * 32 + nt * 8 + (lane & 3) * 2;
            if (r0 < n_valid) {
                float g0 = accg[m][nt][0], u0 = accu[m][nt][0];
                float g1 = accg[m][nt][1], u1 = accu[m][nt][1];
                float2 o = { tf32r((g0 / (1.0f + __expf(-g0))) * u0),
                             tf32r((g1 / (1.0f + __expf(-g1))) * u1) };
                *reinterpret_cast<float2*>(g_act + (size_t)(slot0 + r0) * I_DIM + c) = o;
            }
            if (r0 + 8 < n_valid) {
                float g2 = accg[m][nt][2], u2 = accu[m][nt][2];
                float g3 = accg[m][nt][3], u3 = accu[m][nt][3];
                float2 o = { tf32r((g2 / (1.0f + __expf(-g2))) * u2),
                             tf32r((g3 / (1.0f + __expf(-g3))) * u3) };
                *reinterpret_cast<float2*>(g_act + (size_t)(slot0 + r0 + 8) * I_DIM + c) = o;
            }
        }
    }
}

// ---------------- phase C: out[t] += w_slot * (act @ w2^T) -------------------
__device__ __forceinline__ void dn_load(uint32_t sb, int e, int h0,
                                        int slot0, int k0) {
    int tid = threadIdx.x;
    const float* w2p = g_w2r + ((size_t)e * H_DIM + h0) * I_DIM + k0;
#pragma unroll
    for (int j = 0; j < 4; j++) {
        int idx = tid + j * 256;
        int row = idx >> 3, sl = idx & 7;
        int sr = slot0 + row;
        if (sr >= N_SLOTS) sr = N_SLOTS - 1;
        cpa16(sb + (uint32_t)(row * 144 + sl * 16),
              g_act + (size_t)sr * I_DIM + k0 + sl * 4);
    }
#pragma unroll
    for (int j = 0; j < 4; j++) {
        int idx = tid + j * 256;
        int row = idx >> 3, sl = idx & 7;
        cpa16(sb + TILE_B + (uint32_t)(row * 144 + sl * 16),
              w2p + (size_t)row * I_DIM + sl * 4);
    }
}

__global__ __launch_bounds__(256, 1)
void down_lg(float* __restrict__ out) {
    extern __shared__ float sm[];
    __shared__ int   s_tok[128];
    __shared__ float s_wt[128];

    int e  = blockIdx.y >> 4;
    int ht = blockIdx.y & 15;
    int mt = blockIdx.x;
    int slot0 = g_off[e] + mt * 128;
    int send  = g_off[e + 1];
    if (slot0 >= send) return;
    int n_valid = min(128, send - slot0);
    int h0 = ht * 128;

    int tid = threadIdx.x, lane = tid & 31, warp = tid >> 5;
    int warpM = warp & 1, warpN = warp >> 1;

    for (int r = tid; r < 128; r += 256) {
        bool ok = (r < n_valid);
        s_tok[r] = ok ? g_slot_tok[slot0 + r] : 0;
        s_wt[r]  = ok ? g_slot_w[slot0 + r] : 0.0f;
    }
    __syncthreads();

    uint32_t sb0 = smem_u32(sm);
#pragma unroll
    for (int s = 0; s < DN_STAGES - 1; s++) {
        if (s < KT_DN) dn_load(sb0 + s * DN_STAGE_B, e, h0, slot0, s * BK);
        CP_COMMIT();
    }

    float acc[4][4][4] = {};
    int r4 = lane >> 2;

    for (int kt = 0; kt < KT_DN; kt++) {
        int ldk = kt + DN_STAGES - 1;
        if (ldk < KT_DN)
            dn_load(sb0 + (ldk % DN_STAGES) * DN_STAGE_B, e, h0, slot0, ldk * BK);
        CP_COMMIT();
        CP_WAIT3();
        __syncthreads();

        const float* As = sm + (kt % DN_STAGES) * DN_STAGE_F;
        const float* Bs = As + TILE_F;

#pragma unroll
        for (int kk = 0; kk < 32; kk += 8) {
            int kb = kk + (lane & 3);
            uint32_t a[4][4];
#pragma unroll
            for (int m = 0; m < 4; m++) {
                int rb = warpM * 64 + m * 16 + r4;
                a[m][0] = __float_as_uint(As[rb * RS + kb]);
                a[m][1] = __float_as_uint(As[(rb + 8) * RS + kb]);
                a[m][2] = __float_as_uint(As[rb * RS + kb + 4]);
                a[m][3] = __float_as_uint(As[(rb + 8) * RS + kb + 4]);
            }
#pragma unroll
            for (int nt = 0; nt < 4; nt++) {
                int nb = warpN * 32 + nt * 8 + r4;
                uint32_t b[2] = {__float_as_uint(Bs[nb * RS + kb]),
                                 __float_as_uint(Bs[nb * RS + kb + 4])};
#pragma unroll
                for (int m = 0; m < 4; m++) mma_tf32(acc[m][nt], a[m], b);
            }
        }
        __syncthreads();
    }

    // epilogue: scaled atomic scatter-add into out
#pragma unroll
    for (int m = 0; m < 4; m++) {
#pragma unroll
        for (int nt = 0; nt < 4; nt++) {
            int r0 = warpM * 64 + m * 16 + r4;
            int c  = h0 + warpN * 32 + nt * 8 + (lane & 3) * 2;
            if (r0 < n_valid) {
                int t = s_tok[r0]; float w = s_wt[r0];
                atomicAdd(out + (size_t)t * H_DIM + c,     w * acc[m][nt][0]);
                atomicAdd(out + (size_t)t * H_DIM + c + 1, w * acc[m][nt][1]);
            }
            if (r0 + 8 < n_valid) {
                int t = s_tok[r0 + 8]; float w = s_wt[r0 + 8];
                atomicAdd(out + (size_t)t * H_DIM + c,     w * acc[m][nt][2]);
                atomicAdd(out + (size_t)t * H_DIM + c + 1, w * acc[m][nt][3]);
            }
        }
    }
}

// ---------------- launch ------------------------------------------------------
extern "C" void kernel_launch(void* const* d_in, const int* in_sizes, int n_in,
                              void* d_out, int out_size) {
    const float* hidden = (const float*)d_in[0];
    const float* logits = (const float*)d_in[1];
    const float* w1     = (const float*)d_in[2];
    const float* w3     = (const float*)d_in[3];
    const float* w2     = (const float*)d_in[4];
    float* out = (float*)d_out;

    cudaFuncSetAttribute(gateup_lg, cudaFuncAttributeMaxDynamicSharedMemorySize, GU_SMEM);
    cudaFuncSetAttribute(down_lg,   cudaFuncAttributeMaxDynamicSharedMemorySize, DN_SMEM);

    cudaMemsetAsync(out, 0, (size_t)T_TOK * H_DIM * sizeof(float), 0);

    reset_kernel<<<1, 32>>>();
    route_kernel<<<T_TOK / 256, 256>>>(logits);
    scan_kernel<<<1, 1>>>();
    scatter_kernel<<<T_TOK / 256, 256>>>();

    round_all<<<RND_BLOCKS, 256>>>((const float4*)w1, (const float4*)w3,
                                   (const float4*)w2, (const float4*)hidden);

    dim3 gB(MT, N_EXP * ITILES);   // m fastest: concurrent CTAs share B tiles in L2
    gateup_lg<<<gB, 256, GU_SMEM>>>();

    dim3 gC(MT, N_EXP * HTILES);
    down_lg<<<gC, 256, DN_SMEM>>>(out);
}

// round 4
// speedup vs baseline: 2.4218x; 1.8355x over previous
#include <cuda_runtime.h>
#include <cuda_fp16.h>
#include <cstdint>

#define T_TOK 4096
#define H_DIM 2048
#define I_DIM 4096
#define N_EXP 8
#define TOPK 2
#define N_SLOTS (T_TOK * TOPK)

#define BK 64                    // halves per k-tile
#define RSH 72                   // smem row stride in halves (144B)
#define RSW 36                   // row stride in 32-bit words
#define TILE_B (128 * 144)       // 18432 bytes per 128 x 64h tile
#define MT 32

#define GU_STAGES 4
#define GU_STAGE_B (3 * TILE_B)
#define GU_SMEM (GU_STAGES * GU_STAGE_B)   // 221184
#define ITILES (I_DIM / 128)     // 32
#define KT_GU (H_DIM / BK)       // 32

#define DN_STAGES 4
#define DN_STAGE_B (2 * TILE_B)
#define DN_SMEM (DN_STAGES * DN_STAGE_B)   // 147456
#define HTILES (H_DIM / 128)     // 16
#define KT_DN (I_DIM / BK)       // 64

// ---------------- scratch (static device globals; no allocation) ------------
__device__ int    g_cnt[N_EXP];
__device__ int    g_cur[N_EXP];
__device__ int    g_off[N_EXP + 1];
__device__ int    g_tok_e[N_SLOTS];
__device__ float  g_tok_w[N_SLOTS];
__device__ int    g_slot_tok[N_SLOTS];
__device__ float  g_slot_w[N_SLOTS];
__device__ __half g_act_h[(size_t)N_SLOTS * I_DIM];       // 64MB fp16
__device__ __half g_w1h[(size_t)N_EXP * I_DIM * H_DIM];   // 128MB
__device__ __half g_w3h[(size_t)N_EXP * I_DIM * H_DIM];   // 128MB
__device__ __half g_w2h[(size_t)N_EXP * H_DIM * I_DIM];   // 128MB
__device__ __half g_hidh[(size_t)T_TOK * H_DIM];          // 16MB

// ---------------- helpers ----------------------------------------------------
__device__ __forceinline__ uint32_t smem_u32(const void* p) {
    uint32_t a;
    asm("{ .reg .u64 t; cvta.to.shared.u64 t, %1; cvt.u32.u64 %0, t; }"
        : "=r"(a) : "l"(p));
    return a;
}
__device__ __forceinline__ void cpa16(uint32_t dst, const void* src) {
    asm volatile("cp.async.cg.shared.global [%0], [%1], 16;"
                 :: "r"(dst), "l"(src));
}
#define CP_COMMIT() asm volatile("cp.async.commit_group;" ::: "memory")
#define CP_WAIT3()  asm volatile("cp.async.wait_group 3;" ::: "memory")

__device__ __forceinline__ void mma_f16(float c[4], const uint32_t a[4],
                                        const uint32_t b[2]) {
    asm("mma.sync.aligned.m16n8k16.row.col.f32.f16.f16.f32 "
        "{%0,%1,%2,%3}, {%4,%5,%6,%7}, {%8,%9}, {%0,%1,%2,%3};"
        : "+f"(c[0]), "+f"(c[1]), "+f"(c[2]), "+f"(c[3])
        : "r"(a[0]), "r"(a[1]), "r"(a[2]), "r"(a[3]),
          "r"(b[0]), "r"(b[1]));
}

// ---------------- routing ----------------------------------------------------
__global__ void reset_kernel() {
    int i = threadIdx.x;
    if (i < N_EXP) { g_cnt[i] = 0; g_cur[i] = 0; }
}

__global__ void route_kernel(const float* __restrict__ logits) {
    int t = blockIdx.x * blockDim.x + threadIdx.x;
    if (t >= T_TOK) return;
    float v[N_EXP];
#pragma unroll
    for (int e = 0; e < N_EXP; e++) v[e] = logits[t * N_EXP + e];
    int e0 = 0; float b0 = v[0];
#pragma unroll
    for (int e = 1; e < N_EXP; e++) if (v[e] > b0) { b0 = v[e]; e0 = e; }
    int e1 = -1; float b1 = -3.0e38f;
#pragma unroll
    for (int e = 0; e < N_EXP; e++)
        if (e != e0 && v[e] > b1) { b1 = v[e]; e1 = e; }
    float w1v = __expf(b1 - b0);
    float inv = 1.0f / (1.0f + w1v);
    g_tok_e[2 * t]     = e0;
    g_tok_e[2 * t + 1] = e1;
    g_tok_w[2 * t]     = inv;
    g_tok_w[2 * t + 1] = w1v * inv;
    atomicAdd(&g_cnt[e0], 1);
    atomicAdd(&g_cnt[e1], 1);
}

__global__ void scan_kernel() {
    int acc = 0;
    g_off[0] = 0;
#pragma unroll
    for (int e = 0; e < N_EXP; e++) { acc += g_cnt[e]; g_off[e + 1] = acc; }
}

__global__ void scatter_kernel() {
    int t = blockIdx.x * blockDim.x + threadIdx.x;
    if (t >= T_TOK) return;
#pragma unroll
    for (int k = 0; k < TOPK; k++) {
        int e = g_tok_e[2 * t + k];
        int p = atomicAdd(&g_cur[e], 1);
        int s = g_off[e] + p;
        g_slot_tok[s] = t;
        g_slot_w[s]   = g_tok_w[2 * t + k];
    }
}

// ---------------- pre-pass: fp16 copies of weights + hidden ------------------
#define W_F4 (16777216)          // 64M floats / 4
#define H_F4 (2097152)
#define RND_BLOCKS ((3 * W_F4 + H_F4) / 256)

__global__ void to_half_all(const float4* __restrict__ w1,
                            const float4* __restrict__ w3,
                            const float4* __restrict__ w2,
                            const float4* __restrict__ hid) {
    long long i = (long long)blockIdx.x * 256 + threadIdx.x;
    const float4* s;
    __half2* d;
    if (i < W_F4)          { s = w1 + i;               d = (__half2*)g_w1h + 2 * i; }
    else if (i < 2 * W_F4) { s = w3 + (i - W_F4);      d = (__half2*)g_w3h + 2 * (i - W_F4); }
    else if (i < 3 * W_F4) { s = w2 + (i - 2 * W_F4);  d = (__half2*)g_w2h + 2 * (i - 2 * W_F4); }
    else                   { s = hid + (i - 3 * W_F4); d = (__half2*)g_hidh + 2 * (i - 3 * W_F4); }
    float4 v = *s;
    d[0] = __floats2half2_rn(v.x, v.y);
    d[1] = __floats2half2_rn(v.z, v.w);
}

// ---------------- phase B: act = silu(x @ w1^T) * (x @ w3^T) -----------------
// BM=128, BN=128, BK=64h. 8 warps: warpM=warp&1 (64 rows), warpN=warp>>1 (32 cols).
__device__ __forceinline__ void gu_load(uint32_t sb, int e, int i0,
                                        const int* stok, int k0) {
    int tid = threadIdx.x;
    const __half* w1p = g_w1h + ((size_t)e * I_DIM + i0) * H_DIM + k0;
    const __half* w3p = g_w3h + ((size_t)e * I_DIM + i0) * H_DIM + k0;
#pragma unroll
    for (int j = 0; j < 4; j++) {
        int idx = tid + j * 256;
        int row = idx >> 3, sl = idx & 7;
        cpa16(sb + (uint32_t)(row * 144 + sl * 16),
              g_hidh + (size_t)stok[row] * H_DIM + k0 + sl * 8);
    }
#pragma unroll
    for (int j = 0; j < 4; j++) {
        int idx = tid + j * 256;
        int row = idx >> 3, sl = idx & 7;
        cpa16(sb + TILE_B + (uint32_t)(row * 144 + sl * 16),
              w1p + (size_t)row * H_DIM + sl * 8);
    }
#pragma unroll
    for (int j = 0; j < 4; j++) {
        int idx = tid + j * 256;
        int row = idx >> 3, sl = idx & 7;
        cpa16(sb + 2 * TILE_B + (uint32_t)(row * 144 + sl * 16),
              w3p + (size_t)row * H_DIM + sl * 8);
    }
}

__global__ __launch_bounds__(256, 1)
void gateup_h() {
    extern __shared__ uint32_t smw[];
    __shared__ int s_tok[128];

    int e  = blockIdx.y >> 5;
    int it = blockIdx.y & 31;
    int mt = blockIdx.x;
    int slot0 = g_off[e] + mt * 128;
    int send  = g_off[e + 1];
    if (slot0 >= send) return;
    int n_valid = min(128, send - slot0);
    int i0 = it * 128;

    int tid = threadIdx.x, lane = tid & 31, warp = tid >> 5;
    int warpM = warp & 1, warpN = warp >> 1;
    int r4 = lane >> 2, t4 = lane & 3;

    for (int r = tid; r < 128; r += 256)
        s_tok[r] = (r < n_valid) ? g_slot_tok[slot0 + r] : g_slot_tok[slot0];
    __syncthreads();

    uint32_t sb0 = smem_u32(smw);
#pragma unroll
    for (int s = 0; s < GU_STAGES - 1; s++) {
        if (s < KT_GU) gu_load(sb0 + s * GU_STAGE_B, e, i0, s_tok, s * BK);
        CP_COMMIT();
    }

    float accg[4][4][4] = {};
    float accu[4][4][4] = {};

    for (int kt = 0; kt < KT_GU; kt++) {
        int ldk = kt + GU_STAGES - 1;
        if (ldk < KT_GU)
            gu_load(sb0 + (ldk % GU_STAGES) * GU_STAGE_B, e, i0, s_tok, ldk * BK);
        CP_COMMIT();
        CP_WAIT3();
        __syncthreads();

        const uint32_t* As = smw + (size_t)(kt % GU_STAGES) * (GU_STAGE_B / 4);
        const uint32_t* Bg = As + TILE_B / 4;
        const uint32_t* Bu = As + 2 * (TILE_B / 4);

#pragma unroll
        for (int ks = 0; ks < 4; ks++) {          // k16 steps within BK=64
            int kw = ks * 8 + t4;                 // word offset within row
            uint32_t a[4][4];
#pragma unroll
            for (int m = 0; m < 4; m++) {
                int rb = warpM * 64 + m * 16 + r4;
                a[m][0] = As[rb * RSW + kw];
                a[m][1] = As[(rb + 8) * RSW + kw];
                a[m][2] = As[rb * RSW + kw + 4];
                a[m][3] = As[(rb + 8) * RSW + kw + 4];
            }
#pragma unroll
            for (int nt = 0; nt < 4; nt++) {
                int nb = warpN * 32 + nt * 8 + r4;
                uint32_t bg[2] = { Bg[nb * RSW + kw], Bg[nb * RSW + kw + 4] };
                uint32_t bu[2] = { Bu[nb * RSW + kw], Bu[nb * RSW + kw + 4] };
#pragma unroll
                for (int m = 0; m < 4; m++) {
                    mma_f16(accg[m][nt], a[m], bg);
                    mma_f16(accu[m][nt], a[m], bu);
                }
            }
        }
        __syncthreads();
    }

    // epilogue: silu(gate)*up -> g_act_h
#pragma unroll
    for (int m = 0; m < 4; m++) {
#pragma unroll
        for (int nt = 0; nt < 4; nt++) {
            int r0 = warpM * 64 + m * 16 + r4;
            int c  = i0 + warpN * 32 + nt * 8 + t4 * 2;
            if (r0 < n_valid) {
                float g0 = accg[m][nt][0], u0 = accu[m][nt][0];
                float g1 = accg[m][nt][1], u1 = accu[m][nt][1];
                *reinterpret_cast<__half2*>(g_act_h + (size_t)(slot0 + r0) * I_DIM + c) =
                    __floats2half2_rn((g0 / (1.0f + __expf(-g0))) * u0,
                                      (g1 / (1.0f + __expf(-g1))) * u1);
            }
            if (r0 + 8 < n_valid) {
                float g2 = accg[m][nt][2], u2 = accu[m][nt][2];
                float g3 = accg[m][nt][3], u3 = accu[m][nt][3];
                *reinterpret_cast<__half2*>(g_act_h + (size_t)(slot0 + r0 + 8) * I_DIM + c) =
                    __floats2half2_rn((g2 / (1.0f + __expf(-g2))) * u2,
                                      (g3 / (1.0f + __expf(-g3))) * u3);
            }
        }
    }
}

// ---------------- phase C: out[t] += w_slot * (act @ w2^T) -------------------
__device__ __forceinline__ void dn_load(uint32_t sb, int e, int h0,
                                        int slot0, int k0) {
    int tid = threadIdx.x;
    const __half* w2p = g_w2h + ((size_t)e * H_DIM + h0) * I_DIM + k0;
#pragma unroll
    for (int j = 0; j < 4; j++) {
        int idx = tid + j * 256;
        int row = idx >> 3, sl = idx & 7;
        int sr = slot0 + row;
        if (sr >= N_SLOTS) sr = N_SLOTS - 1;
        cpa16(sb + (uint32_t)(row * 144 + sl * 16),
              g_act_h + (size_t)sr * I_DIM + k0 + sl * 8);
    }
#pragma unroll
    for (int j = 0; j < 4; j++) {
        int idx = tid + j * 256;
        int row = idx >> 3, sl = idx & 7;
        cpa16(sb + TILE_B + (uint32_t)(row * 144 + sl * 16),
              w2p + (size_t)row * I_DIM + sl * 8);
    }
}

__global__ __launch_bounds__(256, 1)
void down_h(float* __restrict__ out) {
    extern __shared__ uint32_t smw[];
    __shared__ int   s_tok[128];
    __shared__ float s_wt[128];

    int e  = blockIdx.y >> 4;
    int ht = blockIdx.y & 15;
    int mt = blockIdx.x;
    int slot0 = g_off[e] + mt * 128;
    int send  = g_off[e + 1];
    if (slot0 >= send) return;
    int n_valid = min(128, send - slot0);
    int h0 = ht * 128;

    int tid = threadIdx.x, lane = tid & 31, warp = tid >> 5;
    int warpM = warp & 1, warpN = warp >> 1;
    int r4 = lane >> 2, t4 = lane & 3;

    for (int r = tid; r < 128; r += 256) {
        bool ok = (r < n_valid);
        s_tok[r] = ok ? g_slot_tok[slot0 + r] : 0;
        s_wt[r]  = ok ? g_slot_w[slot0 + r] : 0.0f;
    }
    __syncthreads();

    uint32_t sb0 = smem_u32(smw);
#pragma unroll
    for (int s = 0; s < DN_STAGES - 1; s++) {
        if (s < KT_DN) dn_load(sb0 + s * DN_STAGE_B, e, h0, slot0, s * BK);
        CP_COMMIT();
    }

    float acc[4][4][4] = {};

    for (int kt = 0; kt < KT_DN; kt++) {
        int ldk = kt + DN_STAGES - 1;
        if (ldk < KT_DN)
            dn_load(sb0 + (ldk % DN_STAGES) * DN_STAGE_B, e, h0, slot0, ldk * BK);
        CP_COMMIT();
        CP_WAIT3();
        __syncthreads();

        const uint32_t* As = smw + (size_t)(kt % DN_STAGES) * (DN_STAGE_B / 4);
        const uint32_t* Bs = As + TILE_B / 4;

#pragma unroll
        for (int ks = 0; ks < 4; ks++) {
            int kw = ks * 8 + t4;
            uint32_t a[4][4];
#pragma unroll
            for (int m = 0; m < 4; m++) {
                int rb = warpM * 64 + m * 16 + r4;
                a[m][0] = As[rb * RSW + kw];
                a[m][1] = As[(rb + 8) * RSW + kw];
                a[m][2] = As[rb * RSW + kw + 4];
                a[m][3] = As[(rb + 8) * RSW + kw + 4];
            }
#pragma unroll
            for (int nt = 0; nt < 4; nt++) {
                int nb = warpN * 32 + nt * 8 + r4;
                uint32_t b[2] = { Bs[nb * RSW + kw], Bs[nb * RSW + kw + 4] };
#pragma unroll
                for (int m = 0; m < 4; m++) mma_f16(acc[m][nt], a[m], b);
            }
        }
        __syncthreads();
    }

    // epilogue: scaled atomic scatter-add
#pragma unroll
    for (int m = 0; m < 4; m++) {
#pragma unroll
        for (int nt = 0; nt < 4; nt++) {
            int r0 = warpM * 64 + m * 16 + r4;
            int c  = h0 + warpN * 32 + nt * 8 + t4 * 2;
            if (r0 < n_valid) {
                int t = s_tok[r0]; float w = s_wt[r0];
                atomicAdd(out + (size_t)t * H_DIM + c,     w * acc[m][nt][0]);
                atomicAdd(out + (size_t)t * H_DIM + c + 1, w * acc[m][nt][1]);
            }
            if (r0 + 8 < n_valid) {
                int t = s_tok[r0 + 8]; float w = s_wt[r0 + 8];
                atomicAdd(out + (size_t)t * H_DIM + c,     w * acc[m][nt][2]);
                atomicAdd(out + (size_t)t * H_DIM + c + 1, w * acc[m][nt][3]);
            }
        }
    }
}

// ---------------- launch ------------------------------------------------------
extern "C" void kernel_launch(void* const* d_in, const int* in_sizes, int n_in,
                              void* d_out, int out_size) {
    const float* hidden = (const float*)d_in[0];
    const float* logits = (const float*)d_in[1];
    const float* w1     = (const float*)d_in[2];
    const float* w3     = (const float*)d_in[3];
    const float* w2     = (const float*)d_in[4];
    float* out = (float*)d_out;

    cudaFuncSetAttribute(gateup_h, cudaFuncAttributeMaxDynamicSharedMemorySize, GU_SMEM);
    cudaFuncSetAttribute(down_h,   cudaFuncAttributeMaxDynamicSharedMemorySize, DN_SMEM);

    cudaMemsetAsync(out, 0, (size_t)T_TOK * H_DIM * sizeof(float), 0);

    reset_kernel<<<1, 32>>>();
    route_kernel<<<T_TOK / 256, 256>>>(logits);
    scan_kernel<<<1, 1>>>();
    scatter_kernel<<<T_TOK / 256, 256>>>();

    to_half_all<<<RND_BLOCKS, 256>>>((const float4*)w1, (const float4*)w3,
                                     (const float4*)w2, (const float4*)hidden);

    dim3 gB(MT, N_EXP * ITILES);
    gateup_h<<<gB, 256, GU_SMEM>>>();

    dim3 gC(MT, N_EXP * HTILES);
    down_h<<<gC, 256, DN_SMEM>>>(out);
}

// round 5
// speedup vs baseline: 2.4397x; 1.0074x over previous
#include <cuda_runtime.h>
#include <cuda_fp16.h>
#include <cstdint>

#define T_TOK 4096
#define H_DIM 2048
#define I_DIM 4096
#define N_EXP 8
#define TOPK 2
#define N_SLOTS (T_TOK * TOPK)

#define BK 64                    // halves per k-tile
#define RSW 36                   // row stride in 32-bit words (144B)
#define TILE_B (128 * 144)       // 18432 bytes per 128 x 64h tile
#define ITILES 32                // I_DIM / 128
#define HTILES 16                // H_DIM / 128
#define KT_GU (H_DIM / BK)       // 32
#define KT_DN (I_DIM / BK)       // 64

#define GU_STAGES 4
#define GU_STAGE_B (3 * TILE_B)
#define GU_SMEM (GU_STAGES * GU_STAGE_B)   // 221184
#define DN_STAGES 4
#define DN_STAGE_B (2 * TILE_B)
#define DN_SMEM (DN_STAGES * DN_STAGE_B)   // 147456

#define NPERS 152               // persistent CTAs
#define W_F4 16777216           // 8*4096*2048/4
#define H_F4 2097152            // 4096*2048/4
#define W2_CHUNKS 512           // w2 conversion chunks (32768 float4 each)

// ---------------- scratch (static device globals; no allocation) ------------
__device__ int    g_cnt[N_EXP];
__device__ int    g_cur[N_EXP];
__device__ int    g_off[N_EXP + 1];
__device__ int    g_tok_e[N_SLOTS];
__device__ float  g_tok_w[N_SLOTS];
__device__ int    g_tok_slot[N_SLOTS];
__device__ int    g_slot_tok[N_SLOTS];
__device__ int    g_qh, g_qd;
__device__ int    g_n_gu, g_n_dn;
__device__ int    g_items_gu[N_EXP * ITILES * 32 + W2_CHUNKS];
__device__ int    g_items_dn[N_EXP * HTILES * 32];
__device__ __half g_act_h[(size_t)N_SLOTS * I_DIM];       // 64MB
__device__ float  g_y[(size_t)N_SLOTS * H_DIM];           // 64MB slot-major down output
__device__ __half g_w1h[(size_t)N_EXP * I_DIM * H_DIM];   // 128MB
__device__ __half g_w3h[(size_t)N_EXP * I_DIM * H_DIM];   // 128MB
__device__ __half g_w2h[(size_t)N_EXP * H_DIM * I_DIM];   // 128MB
__device__ __half g_hidh[(size_t)T_TOK * H_DIM];          // 16MB

// ---------------- helpers ----------------------------------------------------
__device__ __forceinline__ uint32_t smem_u32(const void* p) {
    uint32_t a;
    asm("{ .reg .u64 t; cvta.to.shared.u64 t, %1; cvt.u32.u64 %0, t; }"
        : "=r"(a) : "l"(p));
    return a;
}
__device__ __forceinline__ void cpa16(uint32_t dst, const void* src) {
    asm volatile("cp.async.cg.shared.global [%0], [%1], 16;"
                 :: "r"(dst), "l"(src));
}
#define CP_COMMIT() asm volatile("cp.async.commit_group;" ::: "memory")
#define CP_WAIT3()  asm volatile("cp.async.wait_group 3;" ::: "memory")
#define CP_WAIT0()  asm volatile("cp.async.wait_group 0;" ::: "memory")

__device__ __forceinline__ void mma_f16(float c[4], const uint32_t a[4],
                                        const uint32_t b[2]) {
    asm("mma.sync.aligned.m16n8k16.row.col.f32.f16.f16.f32 "
        "{%0,%1,%2,%3}, {%4,%5,%6,%7}, {%8,%9}, {%0,%1,%2,%3};"
        : "+f"(c[0]), "+f"(c[1]), "+f"(c[2]), "+f"(c[3])
        : "r"(a[0]), "r"(a[1]), "r"(a[2]), "r"(a[3]),
          "r"(b[0]), "r"(b[1]));
}

// ---------------- routing / setup ---------------------------------------------
__global__ void reset_kernel() {
    int i = threadIdx.x;
    if (i < N_EXP) { g_cnt[i] = 0; g_cur[i] = 0; }
}

__device__ __forceinline__ void route_body(const float* __restrict__ logits, int t) {
    float v[N_EXP];
#pragma unroll
    for (int e = 0; e < N_EXP; e++) v[e] = logits[t * N_EXP + e];
    int e0 = 0; float b0 = v[0];
#pragma unroll
    for (int e = 1; e < N_EXP; e++) if (v[e] > b0) { b0 = v[e]; e0 = e; }
    int e1 = -1; float b1 = -3.0e38f;
#pragma unroll
    for (int e = 0; e < N_EXP; e++)
        if (e != e0 && v[e] > b1) { b1 = v[e]; e1 = e; }
    float w1v = __expf(b1 - b0);
    float inv = 1.0f / (1.0f + w1v);
    g_tok_e[2 * t]     = e0;
    g_tok_e[2 * t + 1] = e1;
    g_tok_w[2 * t]     = inv;
    g_tok_w[2 * t + 1] = w1v * inv;
    atomicAdd(&g_cnt[e0], 1);
    atomicAdd(&g_cnt[e1], 1);
}

// merged prepass (w1, w3, hidden -> fp16) + routing (first 16 blocks)
__global__ void prep_route(const float4* __restrict__ w1f,
                           const float4* __restrict__ w3f,
                           const float4* __restrict__ hidf,
                           const float* __restrict__ logits) {
    long long i = (long long)blockIdx.x * 256 + threadIdx.x;
    if (blockIdx.x < 16) route_body(logits, (int)i);

    const float4* s;
    __half2* d;
    if (i < W_F4)          { s = w1f + i;              d = (__half2*)g_w1h + 2 * i; }
    else if (i < 2 * W_F4) { long long k = i - W_F4;   s = w3f + k; d = (__half2*)g_w3h + 2 * k; }
    else                   { long long k = i - 2 * W_F4; s = hidf + k; d = (__half2*)g_hidh + 2 * k; }
    float4 v = *s;
    d[0] = __floats2half2_rn(v.x, v.y);
    d[1] = __floats2half2_rn(v.z, v.w);
}

// prefix scan + work-queue construction (1 block)
__global__ void scan_build() {
    __shared__ int mtc[N_EXP], bgu[N_EXP], bdn[N_EXP], sgu;
    int tid = threadIdx.x;
    if (tid == 0) {
        int acc = 0, tg = 0, td = 0;
        g_off[0] = 0;
        for (int e = 0; e < N_EXP; e++) {
            acc += g_cnt[e]; g_off[e + 1] = acc;
            int m = (g_cnt[e] + 127) >> 7;
            mtc[e] = m;
            bgu[e] = tg; tg += m * ITILES;
            bdn[e] = td; td += m * HTILES;
        }
        sgu = tg;
        g_n_gu = tg + W2_CHUNKS;
        g_n_dn = td;
        g_qh = 0; g_qd = 0;
    }
    __syncthreads();
    for (int e = 0; e < N_EXP; e++) {
        int m = mtc[e];
        int n = m * ITILES;
        for (int j = tid; j < n; j += 256) {
            int it = j / m, mt = j - it * m;       // mt fastest: L2 weight-tile sharing
            g_items_gu[bgu[e] + j] = (e << 11) | (it << 5) | mt;
        }
        int nd = m * HTILES;
        for (int j = tid; j < nd; j += 256) {
            int ht = j / m, mt = j - ht * m;
            g_items_dn[bdn[e] + j] = (e << 9) | (ht << 5) | mt;
        }
    }
    __syncthreads();
    int base = sgu;
    for (int j = tid; j < W2_CHUNKS; j += 256)
        g_items_gu[base + j] = (1 << 30) | j;
}

__global__ void scatter_kernel() {
    int t = blockIdx.x * blockDim.x + threadIdx.x;
    if (t >= T_TOK) return;
#pragma unroll
    for (int k = 0; k < TOPK; k++) {
        int e = g_tok_e[2 * t + k];
        int p = atomicAdd(&g_cur[e], 1);
        int s = g_off[e] + p;
        g_slot_tok[s]     = t;
        g_tok_slot[2 * t + k] = s;
    }
}

// ---------------- phase B: act = silu(x @ w1^T) * (x @ w3^T) -----------------
__device__ __forceinline__ void gu_load(uint32_t sb, int e, int i0,
                                        const int* stok, int k0) {
    int tid = threadIdx.x;
    const __half* w1p = g_w1h + ((size_t)e * I_DIM + i0) * H_DIM + k0;
    const __half* w3p = g_w3h + ((size_t)e * I_DIM + i0) * H_DIM + k0;
#pragma unroll
    for (int j = 0; j < 4; j++) {
        int idx = tid + j * 256;
        int row = idx >> 3, sl = idx & 7;
        cpa16(sb + (uint32_t)(row * 144 + sl * 16),
              g_hidh + (size_t)stok[row] * H_DIM + k0 + sl * 8);
    }
#pragma unroll
    for (int j = 0; j < 4; j++) {
        int idx = tid + j * 256;
        int row = idx >> 3, sl = idx & 7;
        cpa16(sb + TILE_B + (uint32_t)(row * 144 + sl * 16),
              w1p + (size_t)row * H_DIM + sl * 8);
    }
#pragma unroll
    for (int j = 0; j < 4; j++) {
        int idx = tid + j * 256;
        int row = idx >> 3, sl = idx & 7;
        cpa16(sb + 2 * TILE_B + (uint32_t)(row * 144 + sl * 16),
              w3p + (size_t)row * H_DIM + sl * 8);
    }
}

__global__ __launch_bounds__(256, 1)
void gateup_h(const float4* __restrict__ w2f) {
    extern __shared__ uint32_t smw[];
    __shared__ int s_tok[128];
    __shared__ int s_item;

    int tid = threadIdx.x, lane = tid & 31, warp = tid >> 5;
    int warpM = warp & 1, warpN = warp >> 1;
    int r4 = lane >> 2, t4 = lane & 3;
    uint32_t sb0 = smem_u32(smw);
    int n_gu = g_n_gu;

    while (true) {
        __syncthreads();
        if (tid == 0) s_item = atomicAdd(&g_qh, 1);
        __syncthreads();
        int ii = s_item;
        if (ii >= n_gu) return;
        int item = g_items_gu[ii];

        if (item & (1 << 30)) {                 // w2 fp32->fp16 conversion chunk
            int chunk = item & 0x3FF;
            const float4* src = w2f + (size_t)chunk * 32768;
            __half2* dst = (__half2*)g_w2h + (size_t)chunk * 65536;
            for (int j = tid; j < 32768; j += 256) {
                float4 v = src[j];
                dst[2 * j]     = __floats2half2_rn(v.x, v.y);
                dst[2 * j + 1] = __floats2half2_rn(v.z, v.w);
            }
            continue;
        }

        int e  = item >> 11;
        int it = (item >> 5) & 63;
        int mt = item & 31;
        int slot0 = g_off[e] + mt * 128;
        int n_valid = min(128, g_off[e + 1] - slot0);
        int i0 = it * 128;

        for (int r = tid; r < 128; r += 256)
            s_tok[r] = (r < n_valid) ? g_slot_tok[slot0 + r] : g_slot_tok[slot0];
        __syncthreads();

#pragma unroll
        for (int s = 0; s < GU_STAGES - 1; s++) {
            gu_load(sb0 + s * GU_STAGE_B, e, i0, s_tok, s * BK);
            CP_COMMIT();
        }

        float accg[4][4][4] = {};
        float accu[4][4][4] = {};

        for (int kt = 0; kt < KT_GU; kt++) {
            int ldk = kt + GU_STAGES - 1;
            if (ldk < KT_GU)
                gu_load(sb0 + (ldk % GU_STAGES) * GU_STAGE_B, e, i0, s_tok, ldk * BK);
            CP_COMMIT();
            CP_WAIT3();
            __syncthreads();

            const uint32_t* As = smw + (size_t)(kt % GU_STAGES) * (GU_STAGE_B / 4);
            const uint32_t* Bg = As + TILE_B / 4;
            const uint32_t* Bu = As + 2 * (TILE_B / 4);

#pragma unroll
            for (int ks = 0; ks < 4; ks++) {
                int kw = ks * 8 + t4;
                uint32_t a[4][4];
#pragma unroll
                for (int m = 0; m < 4; m++) {
                    int rb = warpM * 64 + m * 16 + r4;
                    a[m][0] = As[rb * RSW + kw];
                    a[m][1] = As[(rb + 8) * RSW + kw];
                    a[m][2] = As[rb * RSW + kw + 4];
                    a[m][3] = As[(rb + 8) * RSW + kw + 4];
                }
#pragma unroll
                for (int nt = 0; nt < 4; nt++) {
                    int nb = warpN * 32 + nt * 8 + r4;
                    uint32_t bg[2] = { Bg[nb * RSW + kw], Bg[nb * RSW + kw + 4] };
                    uint32_t bu[2] = { Bu[nb * RSW + kw], Bu[nb * RSW + kw + 4] };
#pragma unroll
                    for (int m = 0; m < 4; m++) {
                        mma_f16(accg[m][nt], a[m], bg);
                        mma_f16(accu[m][nt], a[m], bu);
                    }
                }
            }
            __syncthreads();
        }
        CP_WAIT0();

        // epilogue: silu(gate)*up -> g_act_h
#pragma unroll
        for (int m = 0; m < 4; m++) {
#pragma unroll
            for (int nt = 0; nt < 4; nt++) {
                int r0 = warpM * 64 + m * 16 + r4;
                int c  = i0 + warpN * 32 + nt * 8 + t4 * 2;
                if (r0 < n_valid) {
                    float g0 = accg[m][nt][0], u0 = accu[m][nt][0];
                    float g1 = accg[m][nt][1], u1 = accu[m][nt][1];
                    *reinterpret_cast<__half2*>(g_act_h + (size_t)(slot0 + r0) * I_DIM + c) =
                        __floats2half2_rn((g0 / (1.0f + __expf(-g0))) * u0,
                                          (g1 / (1.0f + __expf(-g1))) * u1);
                }
                if (r0 + 8 < n_valid) {
                    float g2 = accg[m][nt][2], u2 = accu[m][nt][2];
                    float g3 = accg[m][nt][3], u3 = accu[m][nt][3];
                    *reinterpret_cast<__half2*>(g_act_h + (size_t)(slot0 + r0 + 8) * I_DIM + c) =
                        __floats2half2_rn((g2 / (1.0f + __expf(-g2))) * u2,
                                          (g3 / (1.0f + __expf(-g3))) * u3);
                }
            }
        }
    }
}

// ---------------- phase C: y[slot] = act @ w2^T (slot-major, unweighted) ------
__device__ __forceinline__ void dn_load(uint32_t sb, int e, int h0,
                                        int slot0, int k0) {
    int tid = threadIdx.x;
    const __half* w2p = g_w2h + ((size_t)e * H_DIM + h0) * I_DIM + k0;
#pragma unroll
    for (int j = 0; j < 4; j++) {
        int idx = tid + j * 256;
        int row = idx >> 3, sl = idx & 7;
        int sr = slot0 + row;
        if (sr >= N_SLOTS) sr = N_SLOTS - 1;
        cpa16(sb + (uint32_t)(row * 144 + sl * 16),
              g_act_h + (size_t)sr * I_DIM + k0 + sl * 8);
    }
#pragma unroll
    for (int j = 0; j < 4; j++) {
        int idx = tid + j * 256;
        int row = idx >> 3, sl = idx & 7;
        cpa16(sb + TILE_B + (uint32_t)(row * 144 + sl * 16),
              w2p + (size_t)row * I_DIM + sl * 8);
    }
}

__global__ __launch_bounds__(256, 1)
void down_h() {
    extern __shared__ uint32_t smw[];
    __shared__ int s_item;

    int tid = threadIdx.x, lane = tid & 31, warp = tid >> 5;
    int warpM = warp & 1, warpN = warp >> 1;
    int r4 = lane >> 2, t4 = lane & 3;
    uint32_t sb0 = smem_u32(smw);
    int n_dn = g_n_dn;

    while (true) {
        __syncthreads();
        if (tid == 0) s_item = atomicAdd(&g_qd, 1);
        __syncthreads();
        int ii = s_item;
        if (ii >= n_dn) return;
        int item = g_items_dn[ii];

        int e  = item >> 9;
        int ht = (item >> 5) & 15;
        int mt = item & 31;
        int slot0 = g_off[e] + mt * 128;
        int n_valid = min(128, g_off[e + 1] - slot0);
        int h0 = ht * 128;

#pragma unroll
        for (int s = 0; s < DN_STAGES - 1; s++) {
            dn_load(sb0 + s * DN_STAGE_B, e, h0, slot0, s * BK);
            CP_COMMIT();
        }

        float acc[4][4][4] = {};

        for (int kt = 0; kt < KT_DN; kt++) {
            int ldk = kt + DN_STAGES - 1;
            if (ldk < KT_DN)
                dn_load(sb0 + (ldk % DN_STAGES) * DN_STAGE_B, e, h0, slot0, ldk * BK);
            CP_COMMIT();
            CP_WAIT3();
            __syncthreads();

            const uint32_t* As = smw + (size_t)(kt % DN_STAGES) * (DN_STAGE_B / 4);
            const uint32_t* Bs = As + TILE_B / 4;

#pragma unroll
            for (int ks = 0; ks < 4; ks++) {
                int kw = ks * 8 + t4;
                uint32_t a[4][4];
#pragma unroll
                for (int m = 0; m < 4; m++) {
                    int rb = warpM * 64 + m * 16 + r4;
                    a[m][0] = As[rb * RSW + kw];
                    a[m][1] = As[(rb + 8) * RSW + kw];
                    a[m][2] = As[rb * RSW + kw + 4];
                    a[m][3] = As[(rb + 8) * RSW + kw + 4];
                }
#pragma unroll
                for (int nt = 0; nt < 4; nt++) {
                    int nb = warpN * 32 + nt * 8 + r4;
                    uint32_t b[2] = { Bs[nb * RSW + kw], Bs[nb * RSW + kw + 4] };
#pragma unroll
                    for (int m = 0; m < 4; m++) mma_f16(acc[m][nt], a[m], b);
                }
            }
            __syncthreads();
        }
        CP_WAIT0();

        // epilogue: plain stores into slot-major y
#pragma unroll
        for (int m = 0; m < 4; m++) {
#pragma unroll
            for (int nt = 0; nt < 4; nt++) {
                int r0 = warpM * 64 + m * 16 + r4;
                int c  = h0 + warpN * 32 + nt * 8 + t4 * 2;
                if (r0 < n_valid) {
                    float2 o = { acc[m][nt][0], acc[m][nt][1] };
                    *reinterpret_cast<float2*>(g_y + (size_t)(slot0 + r0) * H_DIM + c) = o;
                }
                if (r0 + 8 < n_valid) {
                    float2 o = { acc[m][nt][2], acc[m][nt][3] };
                    *reinterpret_cast<float2*>(g_y + (size_t)(slot0 + r0 + 8) * H_DIM + c) = o;
                }
            }
        }
    }
}

// ---------------- combine: out[t] = w0*y[s0] + w1*y[s1] ----------------------
__global__ void combine_kernel(float4* __restrict__ out) {
    int i = blockIdx.x * 256 + threadIdx.x;   // float4 index, 2M total
    int t = i >> 9;
    int c = i & 511;
    int s0 = g_tok_slot[2 * t], s1 = g_tok_slot[2 * t + 1];
    float w0 = g_tok_w[2 * t], w1 = g_tok_w[2 * t + 1];
    const float4* y = (const float4*)g_y;
    float4 a = y[(size_t)s0 * 512 + c];
    float4 b = y[(size_t)s1 * 512 + c];
    out[i] = make_float4(w0 * a.x + w1 * b.x, w0 * a.y + w1 * b.y,
                         w0 * a.z + w1 * b.z, w0 * a.w + w1 * b.w);
}

// ---------------- launch ------------------------------------------------------
extern "C" void kernel_launch(void* const* d_in, const int* in_sizes, int n_in,
                              void* d_out, int out_size) {
    const float* hidden = (const float*)d_in[0];
    const float* logits = (const float*)d_in[1];
    const float* w1     = (const float*)d_in[2];
    const float* w3     = (const float*)d_in[3];
    const float* w2     = (const float*)d_in[4];
    float* out = (float*)d_out;

    cudaFuncSetAttribute(gateup_h, cudaFuncAttributeMaxDynamicSharedMemorySize, GU_SMEM);
    cudaFuncSetAttribute(down_h,   cudaFuncAttributeMaxDynamicSharedMemorySize, DN_SMEM);

    reset_kernel<<<1, 32>>>();
    prep_route<<<(2 * W_F4 + H_F4) / 256, 256>>>((const float4*)w1, (const float4*)w3,
                                                 (const float4*)hidden, logits);
    scan_build<<<1, 256>>>();
    scatter_kernel<<<T_TOK / 256, 256>>>();

    gateup_h<<<NPERS, 256, GU_SMEM>>>((const float4*)w2);
    down_h<<<NPERS, 256, DN_SMEM>>>();
    combine_kernel<<<(T_TOK * H_DIM / 4) / 256, 256>>>((float4*)out);
}